// round 2
// baseline (speedup 1.0000x reference)
#include <cuda_runtime.h>
#include <math.h>

#define NLEVELS 16
#define TBL (1 << 18)          // T = 2^18 entries per level
#define PI2 2654435761u

struct Params {
    int ns[NLEVELS];
};

__global__ __launch_bounds__(256)
void hash_enc_kernel(const float2* __restrict__ xy,
                     const float2* __restrict__ tables,   // (L, T) of float2
                     float* __restrict__ out,
                     int B,
                     Params P)
{
    int i = blockIdx.x * blockDim.x + threadIdx.x;
    if (i >= B) return;

    float2 q = xy[i];
    float x = fminf(fmaxf(q.x, 0.0f), 1.0f);
    float y = fminf(fmaxf(q.y, 0.0f), 1.0f);

    float res[2 * NLEVELS];

    #pragma unroll
    for (int l = 0; l < NLEVELS; ++l) {
        const int Nl = P.ns[l];
        const float Nf = (float)Nl;

        float px = x * Nf;
        float py = y * Nf;
        float fx0 = floorf(px);
        float fy0 = floorf(py);
        float wx = px - fx0;
        float wy = py - fy0;

        int x0 = (int)fx0;
        int y0 = (int)fy0;
        int x1 = min(x0 + 1, Nl);
        int y1 = min(y0 + 1, Nl);

        unsigned i00, i10, i01, i11;
        // Dense iff (Nl+1)^2 <= 2^18  <=>  Nl+1 <= 512  <=>  Nl <= 511.
        // (Overflow-free form of the reference's exact-integer test.)
        if (Nl <= 511) {
            unsigned stride = (unsigned)(Nl + 1);
            i00 = (unsigned)x0 * stride + (unsigned)y0;
            i10 = (unsigned)x1 * stride + (unsigned)y0;
            i01 = (unsigned)x0 * stride + (unsigned)y1;
            i11 = (unsigned)x1 * stride + (unsigned)y1;
        } else {
            // hashed: (xi ^ (yi * PI2)) mod T. T = 2^18 divides 2^32, so
            // uint32 wraparound is congruent to the reference's int64 math.
            unsigned hy0 = (unsigned)y0 * PI2;
            unsigned hy1 = (unsigned)y1 * PI2;
            i00 = ((unsigned)x0 ^ hy0) & (TBL - 1);
            i10 = ((unsigned)x1 ^ hy0) & (TBL - 1);
            i01 = ((unsigned)x0 ^ hy1) & (TBL - 1);
            i11 = ((unsigned)x1 ^ hy1) & (TBL - 1);
        }

        const float2* tab = tables + (size_t)l * TBL;
        float2 f00 = __ldg(tab + i00);
        float2 f10 = __ldg(tab + i10);
        float2 f01 = __ldg(tab + i01);
        float2 f11 = __ldg(tab + i11);

        float w00 = (1.0f - wx) * (1.0f - wy);
        float w10 = wx * (1.0f - wy);
        float w01 = (1.0f - wx) * wy;
        float w11 = wx * wy;

        res[2 * l]     = f00.x * w00 + f10.x * w10 + f01.x * w01 + f11.x * w11;
        res[2 * l + 1] = f00.y * w00 + f10.y * w10 + f01.y * w01 + f11.y * w11;
    }

    float4* o = (float4*)(out + (size_t)i * (2 * NLEVELS));
    #pragma unroll
    for (int k = 0; k < 8; ++k) {
        o[k] = make_float4(res[4 * k], res[4 * k + 1], res[4 * k + 2], res[4 * k + 3]);
    }
}

extern "C" void kernel_launch(void* const* d_in, const int* in_sizes, int n_in,
                              void* d_out, int out_size)
{
    const float2* xy     = (const float2*)d_in[0];
    const float2* tables = (const float2*)d_in[1];
    float* out           = (float*)d_out;

    int B = in_sizes[0] / 2;

    // Replicate the reference's NS computation with identical double-precision
    // libm calls (same machine, same libm as the Python reference) so floor()
    // decisions match bit-for-bit.
    Params P;
    double b = exp((log(131072.0) - log(16.0)) / 15.0);
    for (int l = 0; l < NLEVELS; ++l) {
        P.ns[l] = (int)floor(16.0 * pow(b, (double)l));
    }

    const int threads = 256;
    const int blocks = (B + threads - 1) / threads;
    hash_enc_kernel<<<blocks, threads>>>(xy, tables, out, B, P);
}